// round 12
// baseline (speedup 1.0000x reference)
#include <cuda_runtime.h>
#include <cuda_fp16.h>
#include <cuda_fp8.h>
#include <math.h>
#include <stdint.h>

#define BB 8
#define TT 512
#define VV 32128
#define DD 512
#define MM (BB*TT)          /* 4096 tokens */
#define NEG_INF (-1e9f)

// ---------------- scratch (device globals; no allocations allowed) ----------
__device__ uint8_t  g_A8[(size_t)MM * VV];   // 131M e4m3 exp(l); zero-init => invalid rows stay 0
__device__ uint8_t  g_B8[(size_t)DD * VV];   // 16 MB e4m3 (E^T * 64)
__device__ float    g_spred[MM * DD];
__device__ __half   g_pnh[MM * DD];
__device__ __half   g_rnh[MM * DD];
__device__ unsigned g_pmaxo[MM];             // ordered-uint encoded maxes
__device__ unsigned g_rmaxo[MM];

#define NGROUP 63            /* k-groups of 512 vocab columns (last = 384) */
#define EXP_CTAS 128
__device__ int g_cnt[NGROUP];

// ---------------- PTX helpers (legacy-ISA: family-target safe) ----------------
__device__ __forceinline__ uint32_t smem_u32(const void* p) {
    uint32_t a;
    asm("{ .reg .u64 t; cvta.to.shared.u64 t, %1; cvt.u32.u64 %0, t; }" : "=r"(a) : "l"(p));
    return a;
}
__device__ __forceinline__ void cp16(uint32_t dst, const void* src) {
    asm volatile("cp.async.cg.shared.global [%0], [%1], 16;" :: "r"(dst), "l"(src));
}
__device__ __forceinline__ void ldm4(uint32_t* r, uint32_t addr) {
    asm volatile("ldmatrix.sync.aligned.m8n8.x4.shared.b16 {%0,%1,%2,%3}, [%4];"
                 : "=r"(r[0]), "=r"(r[1]), "=r"(r[2]), "=r"(r[3]) : "r"(addr));
}
__device__ __forceinline__ void mma_fp8(float* c, const uint32_t* a, uint32_t b0, uint32_t b1) {
    asm volatile(
        "mma.sync.aligned.m16n8k32.row.col.f32.e4m3.e4m3.f32 "
        "{%0,%1,%2,%3}, {%4,%5,%6,%7}, {%8,%9}, {%0,%1,%2,%3};"
        : "+f"(c[0]), "+f"(c[1]), "+f"(c[2]), "+f"(c[3])
        : "r"(a[0]), "r"(a[1]), "r"(a[2]), "r"(a[3]), "r"(b0), "r"(b1));
}
__device__ __forceinline__ void mma_f16(float* c, const uint32_t* a, uint32_t b0, uint32_t b1) {
    asm volatile(
        "mma.sync.aligned.m16n8k16.row.col.f32.f16.f16.f32 "
        "{%0,%1,%2,%3}, {%4,%5,%6,%7}, {%8,%9}, {%0,%1,%2,%3};"
        : "+f"(c[0]), "+f"(c[1]), "+f"(c[2]), "+f"(c[3])
        : "r"(a[0]), "r"(a[1]), "r"(a[2]), "r"(a[3]), "r"(b0), "r"(b1));
}
// order-preserving float<->uint for atomicMax over signed floats
__device__ __forceinline__ unsigned f2o(float f) {
    unsigned b = __float_as_uint(f);
    return (b & 0x80000000u) ? ~b : (b | 0x80000000u);
}
__device__ __forceinline__ float o2f(unsigned u) {
    unsigned b = (u & 0x80000000u) ? (u ^ 0x80000000u) : ~u;
    return __uint_as_float(b);
}
__device__ __forceinline__ void wait_group_ready(int g) {
    while (true) {
        int v;
        asm volatile("ld.global.acquire.gpu.b32 %0, [%1];" : "=r"(v) : "l"(&g_cnt[g]));
        if (v >= EXP_CTAS) break;
        __nanosleep(64);
    }
}

// ---------------- reductions ----------------
__device__ __forceinline__ float blockReduceSum(float v) {
    __shared__ float sh[32];
    int lane = threadIdx.x & 31, wid = threadIdx.x >> 5;
    #pragma unroll
    for (int o = 16; o; o >>= 1) v += __shfl_xor_sync(0xffffffffu, v, o);
    if (lane == 0) sh[wid] = v;
    __syncthreads();
    int nw = (blockDim.x + 31) >> 5;
    float r = (threadIdx.x < nw) ? sh[threadIdx.x] : 0.0f;
    if (wid == 0) {
        #pragma unroll
        for (int o = 16; o; o >>= 1) r += __shfl_xor_sync(0xffffffffu, r, o);
        if (lane == 0) sh[0] = r;
    }
    __syncthreads();
    float out = sh[0];
    __syncthreads();
    return out;
}

// ---------------- kernel: init flags + max accumulators ----------------------
__global__ void k_init() {
    int i = blockIdx.x * blockDim.x + threadIdx.x;
    if (i < MM) { g_pmaxo[i] = 0u; g_rmaxo[i] = 0u; }
    if (i < NGROUP) g_cnt[i] = 0;
}

// ---------------- kernel 1: persistent exp producer (k-group order) ----------
// 128 CTAs (one wave; all call launch_dependents immediately so the PDL-
// attributed GEMM can start concurrently). CTA c owns rows [c*32, c*32+32);
// sweeps the 63 column-groups in k-order, releasing g_cnt[g] per group.
__global__ void __launch_bounds__(256) k_exp8(const float* __restrict__ logits,
                                              const int* __restrict__ labels) {
    asm volatile("griddepcontrol.launch_dependents;");
    const int tid = threadIdx.x;
    const int row = blockIdx.x * 32 + (tid >> 3);
    const bool valid = (labels[row] != -100);
    const int cbase = (tid & 7) * 64;
    for (int g = 0; g < NGROUP; g++) {
        if (valid) {
            const int c0 = g * 512 + cbase;
            #pragma unroll
            for (int j = 0; j < 8; j++) {
                const int col = c0 + j * 8;
                if (col < VV) {
                    const float* lp = logits + (size_t)row * VV + col;
                    float4 v1 = *reinterpret_cast<const float4*>(lp);
                    float4 v2 = *reinterpret_cast<const float4*>(lp + 4);
                    float4 e1 = make_float4(__expf(v1.x), __expf(v1.y), __expf(v1.z), __expf(v1.w));
                    float4 e2 = make_float4(__expf(v2.x), __expf(v2.y), __expf(v2.z), __expf(v2.w));
                    __nv_fp8x4_e4m3 p1(e1), p2(e2);
                    uint2 o;
                    o.x = *reinterpret_cast<uint32_t*>(&p1);
                    o.y = *reinterpret_cast<uint32_t*>(&p2);
                    *reinterpret_cast<uint2*>(g_A8 + (size_t)row * VV + col) = o;
                }
            }
        }
        __syncthreads();
        if (tid == 0) {
            __threadfence();
            atomicAdd(&g_cnt[g], 1);
        }
    }
}

// ---------------- kernel 0b: transpose E*64 -> E^T e4m3 -----------------
__global__ void k_castB(const float* __restrict__ E) {
    __shared__ float tile[32][33];
    const int v0 = blockIdx.x * 32, d0 = blockIdx.y * 32;
    const int tx = threadIdx.x & 31, ty = threadIdx.x >> 5;   // 8 row-strides
    for (int r = ty; r < 32; r += 8)
        tile[r][tx] = E[(size_t)(v0 + r) * DD + d0 + tx];
    __syncthreads();
    for (int r = ty; r < 32; r += 8) {
        __nv_fp8_e4m3 q(tile[tx][r] * 64.0f);
        g_B8[(size_t)(d0 + r) * VV + v0 + tx] = *reinterpret_cast<uint8_t*>(&q);
    }
}

// ---------------- kernel 2: mma.sync e4m3 GEMM on all 148 SMs -----------------
// Launched with programmatic stream serialization: runs concurrently with
// k_exp8, gated per k-group by g_cnt flags.
#define GM_KC 128
#define GM_ROWB 144                      /* 128 fp8 + 16B pad */
#define GM_AT (112 * GM_ROWB)            /* 16128 */
#define GM_BT (128 * GM_ROWB)            /* 18432 */
#define GM_STG (GM_AT + GM_BT)           /* 34560 */
#define GM_NSTG 3
#define GM_SMEM (GM_NSTG * GM_STG)       /* 103680 */
#define GM_ITERS (VV / GM_KC)            /* 251 */

__global__ void __launch_bounds__(256, 1) k_gemm8() {
    extern __shared__ char smem[];
    const uint32_t sbase = smem_u32(smem);
    const int tid = threadIdx.x;
    const int wid = tid >> 5, lane = tid & 31;
    const int mt = blockIdx.x >> 2, nt = blockIdx.x & 3;
    const int bm = (mt == 36) ? (MM - 112) : mt * 112;
    const int bn = nt * 128;
    const int wn = wid * 16;               // 8 warps cover 128 N

    float c[7][2][4];
    #pragma unroll
    for (int i = 0; i < 7; i++)
        #pragma unroll
        for (int j = 0; j < 2; j++)
            #pragma unroll
            for (int q = 0; q < 4; q++) c[i][j][q] = 0.0f;

    const int msel = lane >> 3, rin = lane & 7;
    const uint32_t aoff = (uint32_t)((((msel & 1) << 3) + rin) * GM_ROWB + ((msel >> 1) << 4));
    const uint32_t boff = (uint32_t)((wn + ((msel >> 1) << 3) + rin) * GM_ROWB + ((msel & 1) << 4));

    // 1920 16B-chunks per stage (A:896, B:1024) / 256 threads
    auto stage_load = [&](int it, int s) {
        const int k0 = it * GM_KC;
        const uint32_t sb = sbase + s * GM_STG;
        #pragma unroll
        for (int i = 0; i < 8; i++) {
            int chunk = tid + (i << 8);
            if (chunk < 896) {
                int row = chunk >> 3, kc = chunk & 7;
                cp16(sb + row * GM_ROWB + kc * 16,
                     g_A8 + (size_t)(bm + row) * VV + k0 + kc * 16);
            } else if (chunk < 1920) {
                int ch = chunk - 896;
                int row = ch >> 3, kc = ch & 7;
                cp16(sb + GM_AT + row * GM_ROWB + kc * 16,
                     g_B8 + (size_t)(bn + row) * VV + k0 + kc * 16);
            }
        }
        asm volatile("cp.async.commit_group;");
    };

    wait_group_ready(0);          // iters 0..3 consume group 0
    stage_load(0, 0);
    stage_load(1, 1);

    uint32_t a[7][4], b[4];
    int s = 0, s2 = 2;

    for (int it = 0; it < GM_ITERS; it++) {
        asm volatile("cp.async.wait_group 1;");
        __syncthreads();

        const int j = it + 2;
        if (j < GM_ITERS) {
            if ((j & 3) == 0) wait_group_ready(j >> 2);
            stage_load(j, s2);
        } else {
            asm volatile("cp.async.commit_group;");
        }

        const uint32_t Ab = sbase + s * GM_STG;
        const uint32_t Bb = Ab + GM_AT;

        #pragma unroll
        for (int ks = 0; ks < 4; ks++) {    // each ks = k32 fp8
            #pragma unroll
            for (int mi = 0; mi < 7; mi++)
                ldm4(a[mi], Ab + aoff + mi * (16 * GM_ROWB) + ks * 32);
            ldm4(b, Bb + boff + ks * 32);
            #pragma unroll
            for (int mi = 0; mi < 7; mi++)
                #pragma unroll
                for (int nj = 0; nj < 2; nj++)
                    mma_fp8(c[mi][nj], a[mi], b[nj * 2], b[nj * 2 + 1]);
        }
        if (++s == GM_NSTG) s = 0;
        if (++s2 == GM_NSTG) s2 = 0;
    }

    const int g = lane >> 2, tg = lane & 3;
    #pragma unroll
    for (int mi = 0; mi < 7; mi++) {
        const int row = bm + mi * 16 + g;
        #pragma unroll
        for (int nj = 0; nj < 2; nj++) {
            const int col = bn + wn + nj * 8 + tg * 2;
            *reinterpret_cast<float2*>(&g_spred[(size_t)row * DD + col]) =
                make_float2(c[mi][nj][0], c[mi][nj][1]);
            *reinterpret_cast<float2*>(&g_spred[(size_t)(row + 8) * DD + col]) =
                make_float2(c[mi][nj][2], c[mi][nj][3]);
        }
    }
}

// ---------------- kernel 3: L2-normalize -> fp16 -----------------------------
__global__ void k_normalize(const float* __restrict__ Emb, const int* __restrict__ labels) {
    const int t = blockIdx.x;
    const int tid = threadIdx.x;   // 128 threads, 4 floats each
    float4 v = reinterpret_cast<const float4*>(g_spred + (size_t)t * DD)[tid];
    float ss = v.x * v.x + v.y * v.y + v.z * v.z + v.w * v.w;
    ss = blockReduceSum(ss);
    float s = 1.0f / fmaxf(sqrtf(ss), 1e-12f);
    __half h[4] = { __float2half(v.x * s), __float2half(v.y * s),
                    __float2half(v.z * s), __float2half(v.w * s) };
    reinterpret_cast<uint2*>(g_pnh + (size_t)t * DD)[tid] = *reinterpret_cast<uint2*>(h);

    int lab = labels[t];
    if (lab == -100) lab = 0;
    float4 w = reinterpret_cast<const float4*>(Emb + (size_t)lab * DD)[tid];
    float ss2 = w.x * w.x + w.y * w.y + w.z * w.z + w.w * w.w;
    ss2 = blockReduceSum(ss2);
    float s2 = 1.0f / fmaxf(sqrtf(ss2), 1e-12f);
    __half h2[4] = { __float2half(w.x * s2), __float2half(w.y * s2),
                     __float2half(w.z * s2), __float2half(w.w * s2) };
    reinterpret_cast<uint2*>(g_rnh + (size_t)t * DD)[tid] = *reinterpret_cast<uint2*>(h2);
}

// ---------------- kernel 4: sim = Pn @ Rn^T with fused masked row/col max ----
#define ROW_BYTES 144
#define TILE_BYTES (128 * ROW_BYTES)       /* 18432 */
#define STAGE_BYTES (2 * TILE_BYTES)       /* 36864 */
#define NSTAGE 4
#define SIM_SMEM (NSTAGE * STAGE_BYTES)    /* 147456 */
#define KC16 64
#define SIM_ITERS (DD / KC16)   /* 8 */

__global__ void __launch_bounds__(256) k_sim_mma(const int* __restrict__ labels) {
    extern __shared__ char smem[];
    __shared__ unsigned char validI[128], validJ[128];
    const uint32_t sbase = smem_u32(smem);
    const int tid = threadIdx.x;
    const int wid = tid >> 5, lane = tid & 31;
    const int b = blockIdx.z;
    const int bm = blockIdx.y * 128;   // pred rows i
    const int bn = blockIdx.x * 128;   // ref rows j
    const int wm = (wid & 1) * 64;
    const int wn = (wid >> 1) * 32;
    const __half* P = g_pnh + (size_t)b * TT * DD;
    const __half* R = g_rnh + (size_t)b * TT * DD;

    if (tid < 128) validI[tid] = (labels[b * TT + bm + tid] != -100) ? 1 : 0;
    else validJ[tid - 128] = (labels[b * TT + bn + tid - 128] != -100) ? 1 : 0;

    float c[4][4][4];
    #pragma unroll
    for (int i = 0; i < 4; i++)
        #pragma unroll
        for (int j = 0; j < 4; j++)
            #pragma unroll
            for (int q = 0; q < 4; q++) c[i][j][q] = 0.0f;

    const int msel = lane >> 3, rin = lane & 7;
    const uint32_t aoff = (uint32_t)((wm + ((msel & 1) << 3) + rin) * ROW_BYTES + ((msel >> 1) << 4));
    const uint32_t boff = (uint32_t)((wn + ((msel >> 1) << 3) + rin) * ROW_BYTES + ((msel & 1) << 4));

    auto stage_load = [&](int it) {
        const int s = it & (NSTAGE - 1);
        const int k0 = it * KC16;
        const uint32_t sb = sbase + s * STAGE_BYTES;
        #pragma unroll
        for (int i = 0; i < 4; i++) {
            int chunk = tid + (i << 8);
            int row = chunk >> 3, col = chunk & 7;
            uint32_t doff = (uint32_t)(row * ROW_BYTES + col * 16);
            cp16(sb + doff,              P + (size_t)(bm + row) * DD + k0 + col * 8);
            cp16(sb + TILE_BYTES + doff, R + (size_t)(bn + row) * DD + k0 + col * 8);
        }
        asm volatile("cp.async.commit_group;");
    };

    stage_load(0);
    stage_load(1);
    stage_load(2);

    for (int it = 0; it < SIM_ITERS; it++) {
        const int s = it & (NSTAGE - 1);
        asm volatile("cp.async.wait_group 2;");
        __syncthreads();

        if (it + 3 < SIM_ITERS) stage_load(it + 3);
        else asm volatile("cp.async.commit_group;");

        const uint32_t Ab = sbase + s * STAGE_BYTES;
        const uint32_t Bb = Ab + TILE_BYTES;

        #pragma unroll
        for (int ks = 0; ks < 4; ks++) {
            uint32_t a[4][4], bfr[2][4];
            #pragma unroll
            for (int mi = 0; mi < 4; mi++)
                ldm4(a[mi], Ab + aoff + mi * (16 * ROW_BYTES) + ks * 32);
            #pragma unroll
            for (int jj = 0; jj < 2; jj++)
                ldm4(bfr[jj], Bb + boff + jj * (16 * ROW_BYTES) + ks * 32);
            #pragma unroll
            for (int mi = 0; mi < 4; mi++)
                #pragma unroll
                for (int nj = 0; nj < 4; nj++) {
                    const uint32_t* bp = &bfr[nj >> 1][(nj & 1) * 2];
                    mma_f16(c[mi][nj], a[mi], bp[0], bp[1]);
                }
        }
    }

    const int g = lane >> 2, tg = lane & 3;

    // ---- fused masked row max (precision) ----
    #pragma unroll
    for (int mi = 0; mi < 4; mi++) {
        const int r0 = wm + mi * 16 + g;      // local row, and r0+8
        float rm0 = NEG_INF, rm1 = NEG_INF;
        #pragma unroll
        for (int nj = 0; nj < 4; nj++) {
            const int c0 = wn + nj * 8 + tg * 2;
            const bool j0 = validJ[c0], j1 = validJ[c0 + 1];
            rm0 = fmaxf(rm0, fmaxf(j0 ? c[mi][nj][0] : NEG_INF, j1 ? c[mi][nj][1] : NEG_INF));
            rm1 = fmaxf(rm1, fmaxf(j0 ? c[mi][nj][2] : NEG_INF, j1 ? c[mi][nj][3] : NEG_INF));
        }
        #pragma unroll
        for (int o = 1; o <= 2; o <<= 1) {
            rm0 = fmaxf(rm0, __shfl_xor_sync(0xffffffffu, rm0, o));
            rm1 = fmaxf(rm1, __shfl_xor_sync(0xffffffffu, rm1, o));
        }
        if (tg == 0) {
            atomicMax(&g_pmaxo[b * TT + bm + r0],     f2o(rm0));
            atomicMax(&g_pmaxo[b * TT + bm + r0 + 8], f2o(rm1));
        }
    }

    // ---- fused masked col max (recall) ----
    #pragma unroll
    for (int nj = 0; nj < 4; nj++) {
        const int c0 = wn + nj * 8 + tg * 2;
        float cm0 = NEG_INF, cm1 = NEG_INF;
        #pragma unroll
        for (int mi = 0; mi < 4; mi++) {
            const int r0 = wm + mi * 16 + g;
            const bool i0 = validI[r0], i1 = validI[r0 + 8];
            cm0 = fmaxf(cm0, fmaxf(i0 ? c[mi][nj][0] : NEG_INF, i1 ? c[mi][nj][2] : NEG_INF));
            cm1 = fmaxf(cm1, fmaxf(i0 ? c[mi][nj][1] : NEG_INF, i1 ? c[mi][nj][3] : NEG_INF));
        }
        #pragma unroll
        for (int o = 4; o <= 16; o <<= 1) {
            cm0 = fmaxf(cm0, __shfl_xor_sync(0xffffffffu, cm0, o));
            cm1 = fmaxf(cm1, __shfl_xor_sync(0xffffffffu, cm1, o));
        }
        if (g == 0) {
            atomicMax(&g_rmaxo[b * TT + bn + c0],     f2o(cm0));
            atomicMax(&g_rmaxo[b * TT + bn + c0 + 1], f2o(cm1));
        }
    }
}

// ---------------- kernel 6: final reduction ----------------
__global__ void k_final(const int* __restrict__ labels, float* __restrict__ out) {
    __shared__ float sp[256], sr[256], sc[256];
    const int tid = threadIdx.x;
    float total = 0.0f;
    for (int b = 0; b < BB; b++) {
        float psum = 0.0f, rsum = 0.0f, cnt = 0.0f;
        for (int idx = tid; idx < TT; idx += 256) {
            if (labels[b * TT + idx] != -100) {
                psum += o2f(g_pmaxo[b * TT + idx]);
                rsum += o2f(g_rmaxo[b * TT + idx]);
                cnt  += 1.0f;
            }
        }
        sp[tid] = psum; sr[tid] = rsum; sc[tid] = cnt;
        __syncthreads();
        for (int s = 128; s > 0; s >>= 1) {
            if (tid < s) {
                sp[tid] += sp[tid + s];
                sr[tid] += sr[tid + s];
                sc[tid] += sc[tid + s];
            }
            __syncthreads();
        }
        if (tid == 0) {
            float cntv = sc[0];
            float dc = fmaxf(cntv, 1.0f);
            float prec = sp[0] / dc;
            float rec  = sr[0] / dc;
            float den = prec + rec;
            float f1 = (den > 0.0f) ? (2.0f * prec * rec / fmaxf(den, 1e-8f)) : 0.0f;
            total += (cntv > 0.0f) ? (1.0f - f1) : 0.0f;
        }
        __syncthreads();
    }
    if (tid == 0) out[0] = total / (float)BB;
}

// ---------------- launch ----------------
extern "C" void kernel_launch(void* const* d_in, const int* in_sizes, int n_in,
                              void* d_out, int out_size) {
    const float* logits = (const float*)d_in[0];   // [8,512,32128] f32
    const int*   labels = (const int*)d_in[1];     // [8,512] i32
    const float* emb    = (const float*)d_in[2];   // [32128,512] f32
    float* out = (float*)d_out;

    cudaFuncSetAttribute(k_gemm8, cudaFuncAttributeMaxDynamicSharedMemorySize, GM_SMEM);
    cudaFuncSetAttribute(k_sim_mma, cudaFuncAttributeMaxDynamicSharedMemorySize, SIM_SMEM);

    k_init<<<(MM + 255) / 256, 256>>>();
    k_castB<<<dim3(VV / 32, DD / 32), 256>>>(emb);
    k_exp8<<<EXP_CTAS, 256>>>(logits, labels);

    // GEMM with programmatic dependent launch: overlaps with k_exp8,
    // correctness gated by g_cnt flags.
    {
        cudaLaunchConfig_t cfg = {};
        cfg.gridDim = dim3(148);
        cfg.blockDim = dim3(256);
        cfg.dynamicSmemBytes = GM_SMEM;
        cfg.stream = 0;
        cudaLaunchAttribute attr[1];
        attr[0].id = cudaLaunchAttributeProgrammaticStreamSerialization;
        attr[0].val.programmaticStreamSerializationAllowed = 1;
        cfg.attrs = attr;
        cfg.numAttrs = 1;
        cudaLaunchKernelEx(&cfg, k_gemm8);
    }

    k_normalize<<<MM, 128>>>(emb, labels);
    k_sim_mma<<<dim3(TT / 128, TT / 128, BB), 256, SIM_SMEM>>>(labels);
    k_final<<<1, 256>>>(labels, out);
}

// round 13
// speedup vs baseline: 1.3753x; 1.3753x over previous
#include <cuda_runtime.h>
#include <cuda_fp16.h>
#include <cuda_fp8.h>
#include <math.h>
#include <stdint.h>

#define BB 8
#define TT 512
#define VV 32128
#define DD 512
#define MM (BB*TT)          /* 4096 tokens */
#define NEG_INF (-1e9f)

// ---------------- scratch (device globals; no allocations allowed) ----------
__device__ uint8_t  g_A8[(size_t)MM * VV];   // 131M e4m3 exp(l); zero-init => invalid rows stay 0
__device__ uint8_t  g_B8[(size_t)DD * VV];   // 16 MB e4m3 (E^T * 64)
__device__ float    g_spred[MM * DD];
__device__ __half   g_pnh[MM * DD];
__device__ __half   g_rnh[MM * DD];
__device__ unsigned g_pmaxo[MM];             // ordered-uint encoded maxes
__device__ unsigned g_rmaxo[MM];

// ---------------- PTX helpers (legacy-ISA: family-target safe) ----------------
__device__ __forceinline__ uint32_t smem_u32(const void* p) {
    uint32_t a;
    asm("{ .reg .u64 t; cvta.to.shared.u64 t, %1; cvt.u32.u64 %0, t; }" : "=r"(a) : "l"(p));
    return a;
}
__device__ __forceinline__ void cp16(uint32_t dst, const void* src) {
    asm volatile("cp.async.cg.shared.global [%0], [%1], 16;" :: "r"(dst), "l"(src));
}
__device__ __forceinline__ void ldm4(uint32_t* r, uint32_t addr) {
    asm volatile("ldmatrix.sync.aligned.m8n8.x4.shared.b16 {%0,%1,%2,%3}, [%4];"
                 : "=r"(r[0]), "=r"(r[1]), "=r"(r[2]), "=r"(r[3]) : "r"(addr));
}
__device__ __forceinline__ void mma_fp8(float* c, const uint32_t* a, uint32_t b0, uint32_t b1) {
    asm volatile(
        "mma.sync.aligned.m16n8k32.row.col.f32.e4m3.e4m3.f32 "
        "{%0,%1,%2,%3}, {%4,%5,%6,%7}, {%8,%9}, {%0,%1,%2,%3};"
        : "+f"(c[0]), "+f"(c[1]), "+f"(c[2]), "+f"(c[3])
        : "r"(a[0]), "r"(a[1]), "r"(a[2]), "r"(a[3]), "r"(b0), "r"(b1));
}
__device__ __forceinline__ void mma_f16(float* c, const uint32_t* a, uint32_t b0, uint32_t b1) {
    asm volatile(
        "mma.sync.aligned.m16n8k16.row.col.f32.f16.f16.f32 "
        "{%0,%1,%2,%3}, {%4,%5,%6,%7}, {%8,%9}, {%0,%1,%2,%3};"
        : "+f"(c[0]), "+f"(c[1]), "+f"(c[2]), "+f"(c[3])
        : "r"(a[0]), "r"(a[1]), "r"(a[2]), "r"(a[3]), "r"(b0), "r"(b1));
}
// order-preserving float<->uint for atomicMax over signed floats
__device__ __forceinline__ unsigned f2o(float f) {
    unsigned b = __float_as_uint(f);
    return (b & 0x80000000u) ? ~b : (b | 0x80000000u);
}
__device__ __forceinline__ float o2f(unsigned u) {
    unsigned b = (u & 0x80000000u) ? (u ^ 0x80000000u) : ~u;
    return __uint_as_float(b);
}

// ---------------- reductions ----------------
__device__ __forceinline__ float blockReduceSum(float v) {
    __shared__ float sh[32];
    int lane = threadIdx.x & 31, wid = threadIdx.x >> 5;
    #pragma unroll
    for (int o = 16; o; o >>= 1) v += __shfl_xor_sync(0xffffffffu, v, o);
    if (lane == 0) sh[wid] = v;
    __syncthreads();
    int nw = (blockDim.x + 31) >> 5;
    float r = (threadIdx.x < nw) ? sh[threadIdx.x] : 0.0f;
    if (wid == 0) {
        #pragma unroll
        for (int o = 16; o; o >>= 1) r += __shfl_xor_sync(0xffffffffu, r, o);
        if (lane == 0) sh[0] = r;
    }
    __syncthreads();
    float out = sh[0];
    __syncthreads();
    return out;
}

// ---------------- kernel: init max accumulators ------------------------------
__global__ void k_init() {
    int i = blockIdx.x * blockDim.x + threadIdx.x;
    if (i < MM) { g_pmaxo[i] = 0u; g_rmaxo[i] = 0u; }
}

// ---------------- kernel 1: exp(l) -> e4m3 (skip invalid rows) ---------------
__global__ void k_exp8(const float* __restrict__ logits, const int* __restrict__ labels) {
    const size_t row = blockIdx.x;
    if (labels[row] == -100) return;      // A8 row stays zero (static init)
    const float* lr = logits + row * (size_t)VV;
    uint8_t* ar = g_A8 + row * (size_t)VV;
    for (int i = threadIdx.x * 8; i < VV; i += blockDim.x * 8) {
        float4 v1 = *reinterpret_cast<const float4*>(lr + i);
        float4 v2 = *reinterpret_cast<const float4*>(lr + i + 4);
        float4 e1 = make_float4(__expf(v1.x), __expf(v1.y), __expf(v1.z), __expf(v1.w));
        float4 e2 = make_float4(__expf(v2.x), __expf(v2.y), __expf(v2.z), __expf(v2.w));
        __nv_fp8x4_e4m3 p1(e1), p2(e2);
        uint2 o;
        o.x = *reinterpret_cast<uint32_t*>(&p1);
        o.y = *reinterpret_cast<uint32_t*>(&p2);
        *reinterpret_cast<uint2*>(ar + i) = o;
    }
}

// ---------------- kernel 0b: transpose E*64 -> E^T e4m3 -----------------
__global__ void k_castB(const float* __restrict__ E) {
    __shared__ float tile[32][33];
    const int v0 = blockIdx.x * 32, d0 = blockIdx.y * 32;
    const int tx = threadIdx.x & 31, ty = threadIdx.x >> 5;   // 8 row-strides
    for (int r = ty; r < 32; r += 8)
        tile[r][tx] = E[(size_t)(v0 + r) * DD + d0 + tx];
    __syncthreads();
    for (int r = ty; r < 32; r += 8) {
        __nv_fp8_e4m3 q(tile[tx][r] * 64.0f);
        g_B8[(size_t)(d0 + r) * VV + v0 + tx] = *reinterpret_cast<uint8_t*>(&q);
    }
}

// ---------------- kernel 2: mma.sync e4m3 GEMM, K-chunk 256 -------------------
// C[4096,512] = exp(L) @ (E*64). 148 CTAs: 37 M-tiles (112 rows; last tile
// overlaps, benign) x 4 N-tiles (128). Warp tile 112x16 (8 warps across N).
// K-chunk 256 fp8 halves iteration count -> amortizes per-iter overhead.
// 3-stage cp.async ring: 191 KB smem, 1 CTA/SM.
#define GM_KC 256
#define GM_ROWB 272                      /* 256 fp8 + 16B pad */
#define GM_AT (112 * GM_ROWB)            /* 30464 */
#define GM_BT (128 * GM_ROWB)            /* 34816 */
#define GM_STG (GM_AT + GM_BT)           /* 65280 */
#define GM_NSTG 3
#define GM_SMEM (GM_NSTG * GM_STG)       /* 195840 */
#define GM_ITERS (VV / GM_KC)            /* 125.5 -> 125 full + tail 128 */
#define GM_FULL (VV / GM_KC)             /* 125 */
/* VV = 32128 = 125*256 + 128: last partial chunk handled as one extra
   128-wide iteration reusing the same smem layout (cols beyond 128 unused). */

__global__ void __launch_bounds__(256, 1) k_gemm8() {
    extern __shared__ char smem[];
    const uint32_t sbase = smem_u32(smem);
    const int tid = threadIdx.x;
    const int wid = tid >> 5, lane = tid & 31;
    const int mt = blockIdx.x >> 2, nt = blockIdx.x & 3;
    const int bm = (mt == 36) ? (MM - 112) : mt * 112;
    const int bn = nt * 128;
    const int wn = wid * 16;               // 8 warps cover 128 N

    float c[7][2][4];
    #pragma unroll
    for (int i = 0; i < 7; i++)
        #pragma unroll
        for (int j = 0; j < 2; j++)
            #pragma unroll
            for (int q = 0; q < 4; q++) c[i][j][q] = 0.0f;

    const int msel = lane >> 3, rin = lane & 7;
    const uint32_t aoff = (uint32_t)((((msel & 1) << 3) + rin) * GM_ROWB + ((msel >> 1) << 4));
    const uint32_t boff = (uint32_t)((wn + ((msel >> 1) << 3) + rin) * GM_ROWB + ((msel & 1) << 4));

    // full stage: A 1792 chunks + B 2048 chunks = 3840 / 256 thr = 15 each
    auto stage_load = [&](int it, int s) {
        const int k0 = it * GM_KC;
        const uint32_t sb = sbase + s * GM_STG;
        #pragma unroll
        for (int i = 0; i < 15; i++) {
            int chunk = tid + (i << 8);
            if (chunk < 1792) {
                int row = chunk >> 4, kc = chunk & 15;
                cp16(sb + row * GM_ROWB + kc * 16,
                     g_A8 + (size_t)(bm + row) * VV + k0 + kc * 16);
            } else {
                int ch = chunk - 1792;
                int row = ch >> 4, kc = ch & 15;
                cp16(sb + GM_AT + row * GM_ROWB + kc * 16,
                     g_B8 + (size_t)(bn + row) * VV + k0 + kc * 16);
            }
        }
        asm volatile("cp.async.commit_group;");
    };
    // tail stage: 128 fp8 columns only (8 kc chunks per row)
    auto stage_load_tail = [&](int s) {
        const int k0 = GM_FULL * GM_KC;   // 32000
        const uint32_t sb = sbase + s * GM_STG;
        #pragma unroll
        for (int i = 0; i < 8; i++) {
            int chunk = tid + (i << 8);
            if (chunk < 896) {
                int row = chunk >> 3, kc = chunk & 7;
                cp16(sb + row * GM_ROWB + kc * 16,
                     g_A8 + (size_t)(bm + row) * VV + k0 + kc * 16);
            } else if (chunk < 1920) {
                int ch = chunk - 896;
                int row = ch >> 3, kc = ch & 7;
                cp16(sb + GM_AT + row * GM_ROWB + kc * 16,
                     g_B8 + (size_t)(bn + row) * VV + k0 + kc * 16);
            }
        }
        asm volatile("cp.async.commit_group;");
    };

    stage_load(0, 0);
    stage_load(1, 1);

    uint32_t a[7][4], b[4];
    int s = 0, s2 = 2;

    for (int it = 0; it <= GM_FULL; it++) {     // 125 full + 1 tail
        asm volatile("cp.async.wait_group 1;");
        __syncthreads();

        const int j = it + 2;
        if (j < GM_FULL) stage_load(j, s2);
        else if (j == GM_FULL) stage_load_tail(s2);
        else asm volatile("cp.async.commit_group;");

        const uint32_t Ab = sbase + s * GM_STG;
        const uint32_t Bb = Ab + GM_AT;
        const int nks = (it == GM_FULL) ? 4 : 8;

        for (int ks = 0; ks < nks; ks++) {    // each ks = k32 fp8
            #pragma unroll
            for (int mi = 0; mi < 7; mi++)
                ldm4(a[mi], Ab + aoff + mi * (16 * GM_ROWB) + ks * 32);
            ldm4(b, Bb + boff + ks * 32);
            #pragma unroll
            for (int mi = 0; mi < 7; mi++)
                #pragma unroll
                for (int nj = 0; nj < 2; nj++)
                    mma_fp8(c[mi][nj], a[mi], b[nj * 2], b[nj * 2 + 1]);
        }
        if (++s == GM_NSTG) s = 0;
        if (++s2 == GM_NSTG) s2 = 0;
    }

    const int g = lane >> 2, tg = lane & 3;
    #pragma unroll
    for (int mi = 0; mi < 7; mi++) {
        const int row = bm + mi * 16 + g;
        #pragma unroll
        for (int nj = 0; nj < 2; nj++) {
            const int col = bn + wn + nj * 8 + tg * 2;
            *reinterpret_cast<float2*>(&g_spred[(size_t)row * DD + col]) =
                make_float2(c[mi][nj][0], c[mi][nj][1]);
            *reinterpret_cast<float2*>(&g_spred[(size_t)(row + 8) * DD + col]) =
                make_float2(c[mi][nj][2], c[mi][nj][3]);
        }
    }
}

// ---------------- kernel 3: L2-normalize -> fp16 -----------------------------
__global__ void k_normalize(const float* __restrict__ Emb, const int* __restrict__ labels) {
    const int t = blockIdx.x;
    const int tid = threadIdx.x;   // 128 threads, 4 floats each
    float4 v = reinterpret_cast<const float4*>(g_spred + (size_t)t * DD)[tid];
    float ss = v.x * v.x + v.y * v.y + v.z * v.z + v.w * v.w;
    ss = blockReduceSum(ss);
    float s = 1.0f / fmaxf(sqrtf(ss), 1e-12f);
    __half h[4] = { __float2half(v.x * s), __float2half(v.y * s),
                    __float2half(v.z * s), __float2half(v.w * s) };
    reinterpret_cast<uint2*>(g_pnh + (size_t)t * DD)[tid] = *reinterpret_cast<uint2*>(h);

    int lab = labels[t];
    if (lab == -100) lab = 0;
    float4 w = reinterpret_cast<const float4*>(Emb + (size_t)lab * DD)[tid];
    float ss2 = w.x * w.x + w.y * w.y + w.z * w.z + w.w * w.w;
    ss2 = blockReduceSum(ss2);
    float s2 = 1.0f / fmaxf(sqrtf(ss2), 1e-12f);
    __half h2[4] = { __float2half(w.x * s2), __float2half(w.y * s2),
                     __float2half(w.z * s2), __float2half(w.w * s2) };
    reinterpret_cast<uint2*>(g_rnh + (size_t)t * DD)[tid] = *reinterpret_cast<uint2*>(h2);
}

// ---------------- kernel 4: sim = Pn @ Rn^T with fused masked row/col max ----
#define ROW_BYTES 144
#define TILE_BYTES (128 * ROW_BYTES)       /* 18432 */
#define STAGE_BYTES (2 * TILE_BYTES)       /* 36864 */
#define NSTAGE 4
#define SIM_SMEM (NSTAGE * STAGE_BYTES)    /* 147456 */
#define KC16 64
#define SIM_ITERS (DD / KC16)   /* 8 */

__global__ void __launch_bounds__(256) k_sim_mma(const int* __restrict__ labels) {
    extern __shared__ char smem[];
    __shared__ unsigned char validI[128], validJ[128];
    const uint32_t sbase = smem_u32(smem);
    const int tid = threadIdx.x;
    const int wid = tid >> 5, lane = tid & 31;
    const int b = blockIdx.z;
    const int bm = blockIdx.y * 128;   // pred rows i
    const int bn = blockIdx.x * 128;   // ref rows j
    const int wm = (wid & 1) * 64;
    const int wn = (wid >> 1) * 32;
    const __half* P = g_pnh + (size_t)b * TT * DD;
    const __half* R = g_rnh + (size_t)b * TT * DD;

    if (tid < 128) validI[tid] = (labels[b * TT + bm + tid] != -100) ? 1 : 0;
    else validJ[tid - 128] = (labels[b * TT + bn + tid - 128] != -100) ? 1 : 0;

    float c[4][4][4];
    #pragma unroll
    for (int i = 0; i < 4; i++)
        #pragma unroll
        for (int j = 0; j < 4; j++)
            #pragma unroll
            for (int q = 0; q < 4; q++) c[i][j][q] = 0.0f;

    const int msel = lane >> 3, rin = lane & 7;
    const uint32_t aoff = (uint32_t)((wm + ((msel & 1) << 3) + rin) * ROW_BYTES + ((msel >> 1) << 4));
    const uint32_t boff = (uint32_t)((wn + ((msel >> 1) << 3) + rin) * ROW_BYTES + ((msel & 1) << 4));

    auto stage_load = [&](int it) {
        const int s = it & (NSTAGE - 1);
        const int k0 = it * KC16;
        const uint32_t sb = sbase + s * STAGE_BYTES;
        #pragma unroll
        for (int i = 0; i < 4; i++) {
            int chunk = tid + (i << 8);
            int row = chunk >> 3, col = chunk & 7;
            uint32_t doff = (uint32_t)(row * ROW_BYTES + col * 16);
            cp16(sb + doff,              P + (size_t)(bm + row) * DD + k0 + col * 8);
            cp16(sb + TILE_BYTES + doff, R + (size_t)(bn + row) * DD + k0 + col * 8);
        }
        asm volatile("cp.async.commit_group;");
    };

    stage_load(0);
    stage_load(1);
    stage_load(2);

    for (int it = 0; it < SIM_ITERS; it++) {
        const int s = it & (NSTAGE - 1);
        asm volatile("cp.async.wait_group 2;");
        __syncthreads();

        if (it + 3 < SIM_ITERS) stage_load(it + 3);
        else asm volatile("cp.async.commit_group;");

        const uint32_t Ab = sbase + s * STAGE_BYTES;
        const uint32_t Bb = Ab + TILE_BYTES;

        #pragma unroll
        for (int ks = 0; ks < 4; ks++) {
            uint32_t a[4][4], bfr[2][4];
            #pragma unroll
            for (int mi = 0; mi < 4; mi++)
                ldm4(a[mi], Ab + aoff + mi * (16 * ROW_BYTES) + ks * 32);
            #pragma unroll
            for (int jj = 0; jj < 2; jj++)
                ldm4(bfr[jj], Bb + boff + jj * (16 * ROW_BYTES) + ks * 32);
            #pragma unroll
            for (int mi = 0; mi < 4; mi++)
                #pragma unroll
                for (int nj = 0; nj < 4; nj++) {
                    const uint32_t* bp = &bfr[nj >> 1][(nj & 1) * 2];
                    mma_f16(c[mi][nj], a[mi], bp[0], bp[1]);
                }
        }
    }

    const int g = lane >> 2, tg = lane & 3;

    // ---- fused masked row max (precision) ----
    #pragma unroll
    for (int mi = 0; mi < 4; mi++) {
        const int r0 = wm + mi * 16 + g;      // local row, and r0+8
        float rm0 = NEG_INF, rm1 = NEG_INF;
        #pragma unroll
        for (int nj = 0; nj < 4; nj++) {
            const int c0 = wn + nj * 8 + tg * 2;
            const bool j0 = validJ[c0], j1 = validJ[c0 + 1];
            rm0 = fmaxf(rm0, fmaxf(j0 ? c[mi][nj][0] : NEG_INF, j1 ? c[mi][nj][1] : NEG_INF));
            rm1 = fmaxf(rm1, fmaxf(j0 ? c[mi][nj][2] : NEG_INF, j1 ? c[mi][nj][3] : NEG_INF));
        }
        #pragma unroll
        for (int o = 1; o <= 2; o <<= 1) {
            rm0 = fmaxf(rm0, __shfl_xor_sync(0xffffffffu, rm0, o));
            rm1 = fmaxf(rm1, __shfl_xor_sync(0xffffffffu, rm1, o));
        }
        if (tg == 0) {
            atomicMax(&g_pmaxo[b * TT + bm + r0],     f2o(rm0));
            atomicMax(&g_pmaxo[b * TT + bm + r0 + 8], f2o(rm1));
        }
    }

    // ---- fused masked col max (recall) ----
    #pragma unroll
    for (int nj = 0; nj < 4; nj++) {
        const int c0 = wn + nj * 8 + tg * 2;
        float cm0 = NEG_INF, cm1 = NEG_INF;
        #pragma unroll
        for (int mi = 0; mi < 4; mi++) {
            const int r0 = wm + mi * 16 + g;
            const bool i0 = validI[r0], i1 = validI[r0 + 8];
            cm0 = fmaxf(cm0, fmaxf(i0 ? c[mi][nj][0] : NEG_INF, i1 ? c[mi][nj][2] : NEG_INF));
            cm1 = fmaxf(cm1, fmaxf(i0 ? c[mi][nj][1] : NEG_INF, i1 ? c[mi][nj][3] : NEG_INF));
        }
        #pragma unroll
        for (int o = 4; o <= 16; o <<= 1) {
            cm0 = fmaxf(cm0, __shfl_xor_sync(0xffffffffu, cm0, o));
            cm1 = fmaxf(cm1, __shfl_xor_sync(0xffffffffu, cm1, o));
        }
        if (g == 0) {
            atomicMax(&g_rmaxo[b * TT + bn + c0],     f2o(cm0));
            atomicMax(&g_rmaxo[b * TT + bn + c0 + 1], f2o(cm1));
        }
    }
}

// ---------------- kernel 6: final reduction ----------------
__global__ void k_final(const int* __restrict__ labels, float* __restrict__ out) {
    __shared__ float sp[256], sr[256], sc[256];
    const int tid = threadIdx.x;
    float total = 0.0f;
    for (int b = 0; b < BB; b++) {
        float psum = 0.0f, rsum = 0.0f, cnt = 0.0f;
        for (int idx = tid; idx < TT; idx += 256) {
            if (labels[b * TT + idx] != -100) {
                psum += o2f(g_pmaxo[b * TT + idx]);
                rsum += o2f(g_rmaxo[b * TT + idx]);
                cnt  += 1.0f;
            }
        }
        sp[tid] = psum; sr[tid] = rsum; sc[tid] = cnt;
        __syncthreads();
        for (int s = 128; s > 0; s >>= 1) {
            if (tid < s) {
                sp[tid] += sp[tid + s];
                sr[tid] += sr[tid + s];
                sc[tid] += sc[tid + s];
            }
            __syncthreads();
        }
        if (tid == 0) {
            float cntv = sc[0];
            float dc = fmaxf(cntv, 1.0f);
            float prec = sp[0] / dc;
            float rec  = sr[0] / dc;
            float den = prec + rec;
            float f1 = (den > 0.0f) ? (2.0f * prec * rec / fmaxf(den, 1e-8f)) : 0.0f;
            total += (cntv > 0.0f) ? (1.0f - f1) : 0.0f;
        }
        __syncthreads();
    }
    if (tid == 0) out[0] = total / (float)BB;
}

// ---------------- launch ----------------
extern "C" void kernel_launch(void* const* d_in, const int* in_sizes, int n_in,
                              void* d_out, int out_size) {
    const float* logits = (const float*)d_in[0];   // [8,512,32128] f32
    const int*   labels = (const int*)d_in[1];     // [8,512] i32
    const float* emb    = (const float*)d_in[2];   // [32128,512] f32
    float* out = (float*)d_out;

    cudaFuncSetAttribute(k_gemm8, cudaFuncAttributeMaxDynamicSharedMemorySize, GM_SMEM);
    cudaFuncSetAttribute(k_sim_mma, cudaFuncAttributeMaxDynamicSharedMemorySize, SIM_SMEM);

    k_init<<<(MM + 255) / 256, 256>>>();
    k_castB<<<dim3(VV / 32, DD / 32), 256>>>(emb);
    k_exp8<<<MM, 256>>>(logits, labels);
    k_gemm8<<<148, 256, GM_SMEM>>>();
    k_normalize<<<MM, 128>>>(emb, labels);
    k_sim_mma<<<dim3(TT / 128, TT / 128, BB), 256, SIM_SMEM>>>(labels);
    k_final<<<1, 256>>>(labels, out);
}

// round 14
// speedup vs baseline: 1.4099x; 1.0251x over previous
#include <cuda_runtime.h>
#include <cuda_fp16.h>
#include <cuda_fp8.h>
#include <math.h>
#include <stdint.h>

#define BB 8
#define TT 512
#define VV 32128
#define DD 512
#define MM (BB*TT)          /* 4096 tokens */
#define NEG_INF (-1e9f)

// ---------------- scratch (device globals; no allocations allowed) ----------
__device__ uint8_t  g_A8[(size_t)MM * VV];   // 131M e4m3 exp(l); zero-init => invalid rows stay 0
__device__ uint8_t  g_B8[(size_t)DD * VV];   // 16 MB e4m3 (E^T * 64)
__device__ float    g_spred[MM * DD];
__device__ __half   g_pnh[MM * DD];
__device__ __half   g_rnh[MM * DD];
__device__ unsigned g_pmaxo[MM];             // ordered-uint encoded maxes
__device__ unsigned g_rmaxo[MM];

// ---------------- PTX helpers (legacy-ISA: family-target safe) ----------------
__device__ __forceinline__ uint32_t smem_u32(const void* p) {
    uint32_t a;
    asm("{ .reg .u64 t; cvta.to.shared.u64 t, %1; cvt.u32.u64 %0, t; }" : "=r"(a) : "l"(p));
    return a;
}
__device__ __forceinline__ void cp16(uint32_t dst, const void* src) {
    asm volatile("cp.async.cg.shared.global [%0], [%1], 16;" :: "r"(dst), "l"(src));
}
__device__ __forceinline__ void ldm4(uint32_t* r, uint32_t addr) {
    asm volatile("ldmatrix.sync.aligned.m8n8.x4.shared.b16 {%0,%1,%2,%3}, [%4];"
                 : "=r"(r[0]), "=r"(r[1]), "=r"(r[2]), "=r"(r[3]) : "r"(addr));
}
__device__ __forceinline__ void mma_fp8(float* c, const uint32_t* a, uint32_t b0, uint32_t b1) {
    asm volatile(
        "mma.sync.aligned.m16n8k32.row.col.f32.e4m3.e4m3.f32 "
        "{%0,%1,%2,%3}, {%4,%5,%6,%7}, {%8,%9}, {%0,%1,%2,%3};"
        : "+f"(c[0]), "+f"(c[1]), "+f"(c[2]), "+f"(c[3])
        : "r"(a[0]), "r"(a[1]), "r"(a[2]), "r"(a[3]), "r"(b0), "r"(b1));
}
__device__ __forceinline__ void mma_f16(float* c, const uint32_t* a, uint32_t b0, uint32_t b1) {
    asm volatile(
        "mma.sync.aligned.m16n8k16.row.col.f32.f16.f16.f32 "
        "{%0,%1,%2,%3}, {%4,%5,%6,%7}, {%8,%9}, {%0,%1,%2,%3};"
        : "+f"(c[0]), "+f"(c[1]), "+f"(c[2]), "+f"(c[3])
        : "r"(a[0]), "r"(a[1]), "r"(a[2]), "r"(a[3]), "r"(b0), "r"(b1));
}
// order-preserving float<->uint for atomicMax over signed floats
__device__ __forceinline__ unsigned f2o(float f) {
    unsigned b = __float_as_uint(f);
    return (b & 0x80000000u) ? ~b : (b | 0x80000000u);
}
__device__ __forceinline__ float o2f(unsigned u) {
    unsigned b = (u & 0x80000000u) ? (u ^ 0x80000000u) : ~u;
    return __uint_as_float(b);
}

// ---------------- fused prologue: init flags + castB + exp8 -------------------
// grid = 16 (init) + 502 (castB) + 4096 (exp8) = 4614 CTAs, 256 threads.
#define PRO_INIT 16
#define PRO_CAST 502          /* VV/32 x DD/32 / 8-stride handled per CTA pair */
#define CAST_VX (VV / 32)     /* 1004 x-tiles; we pack 2 per CTA: 502 CTAs */

__global__ void __launch_bounds__(256) k_prologue(const float* __restrict__ logits,
                                                  const int* __restrict__ labels,
                                                  const float* __restrict__ E) {
    const int bid = blockIdx.x;
    const int tid = threadIdx.x;

    if (bid < PRO_INIT) {
        int i = bid * 256 + tid;
        if (i < MM) { g_pmaxo[i] = 0u; g_rmaxo[i] = 0u; }
        return;
    }
    if (bid < PRO_INIT + 8032) {
        // castB role: 8032 tiles of 32x32 = (VV/32=1004) x (DD/32=16) /2 per CTA
        __shared__ float tile[2][32][33];
        const int t2 = (bid - PRO_INIT) * 2;
        #pragma unroll
        for (int h = 0; h < 2; h++) {
            const int t = t2 + h;
            const int v0 = (t % CAST_VX) * 32, d0 = (t / CAST_VX) * 32;
            const int tx = tid & 31, ty = tid >> 5;
            for (int r = ty; r < 32; r += 8)
                tile[h][r][tx] = E[(size_t)(v0 + r) * DD + d0 + tx];
            __syncthreads();
            for (int r = ty; r < 32; r += 8) {
                __nv_fp8_e4m3 q(tile[h][tx][r] * 64.0f);
                g_B8[(size_t)(d0 + r) * VV + v0 + tx] = *reinterpret_cast<uint8_t*>(&q);
            }
            __syncthreads();
        }
        return;
    }
    // exp8 role
    const size_t row = bid - PRO_INIT - 8032;
    if (labels[row] == -100) return;      // A8 row stays zero (static init)
    const float* lr = logits + row * (size_t)VV;
    uint8_t* ar = g_A8 + row * (size_t)VV;
    for (int i = tid * 8; i < VV; i += 256 * 8) {
        float4 v1 = *reinterpret_cast<const float4*>(lr + i);
        float4 v2 = *reinterpret_cast<const float4*>(lr + i + 4);
        float4 e1 = make_float4(__expf(v1.x), __expf(v1.y), __expf(v1.z), __expf(v1.w));
        float4 e2 = make_float4(__expf(v2.x), __expf(v2.y), __expf(v2.z), __expf(v2.w));
        __nv_fp8x4_e4m3 p1(e1), p2(e2);
        uint2 o;
        o.x = *reinterpret_cast<uint32_t*>(&p1);
        o.y = *reinterpret_cast<uint32_t*>(&p2);
        *reinterpret_cast<uint2*>(ar + i) = o;
    }
}
#define PRO_GRID (PRO_INIT + 8032 + MM)
/* castB tiles: (VV/32)*(DD/32) = 1004*16 = 16064 tiles / 2 per CTA = 8032 CTAs */

// ---------------- kernel 2: mma.sync e4m3 GEMM (R11-best mainloop) ------------
#define GM_KC 128
#define GM_ROWB 144                      /* 128 fp8 + 16B pad */
#define GM_AT (112 * GM_ROWB)            /* 16128 */
#define GM_BT (128 * GM_ROWB)            /* 18432 */
#define GM_STG (GM_AT + GM_BT)           /* 34560 */
#define GM_NSTG 3
#define GM_SMEM (GM_NSTG * GM_STG)       /* 103680 */
#define GM_ITERS (VV / GM_KC)            /* 251 */

__global__ void __launch_bounds__(256, 1) k_gemm8() {
    extern __shared__ char smem[];
    const uint32_t sbase = smem_u32(smem);
    const int tid = threadIdx.x;
    const int wid = tid >> 5, lane = tid & 31;
    const int mt = blockIdx.x >> 2, nt = blockIdx.x & 3;
    const int bm = (mt == 36) ? (MM - 112) : mt * 112;
    const int bn = nt * 128;
    const int wn = wid * 16;               // 8 warps cover 128 N

    float c[7][2][4];
    #pragma unroll
    for (int i = 0; i < 7; i++)
        #pragma unroll
        for (int j = 0; j < 2; j++)
            #pragma unroll
            for (int q = 0; q < 4; q++) c[i][j][q] = 0.0f;

    const int msel = lane >> 3, rin = lane & 7;
    const uint32_t aoff = (uint32_t)((((msel & 1) << 3) + rin) * GM_ROWB + ((msel >> 1) << 4));
    const uint32_t boff = (uint32_t)((wn + ((msel >> 1) << 3) + rin) * GM_ROWB + ((msel & 1) << 4));

    auto stage_load = [&](int it, int s) {
        const int k0 = it * GM_KC;
        const uint32_t sb = sbase + s * GM_STG;
        #pragma unroll
        for (int i = 0; i < 8; i++) {
            int chunk = tid + (i << 8);
            if (chunk < 896) {
                int row = chunk >> 3, kc = chunk & 7;
                cp16(sb + row * GM_ROWB + kc * 16,
                     g_A8 + (size_t)(bm + row) * VV + k0 + kc * 16);
            } else if (chunk < 1920) {
                int ch = chunk - 896;
                int row = ch >> 3, kc = ch & 7;
                cp16(sb + GM_AT + row * GM_ROWB + kc * 16,
                     g_B8 + (size_t)(bn + row) * VV + k0 + kc * 16);
            }
        }
        asm volatile("cp.async.commit_group;");
    };

    stage_load(0, 0);
    stage_load(1, 1);

    uint32_t a[7][4], b[4];
    int s = 0, s2 = 2;

    for (int it = 0; it < GM_ITERS; it++) {
        asm volatile("cp.async.wait_group 1;");
        __syncthreads();

        if (it + 2 < GM_ITERS) stage_load(it + 2, s2);
        else asm volatile("cp.async.commit_group;");

        const uint32_t Ab = sbase + s * GM_STG;
        const uint32_t Bb = Ab + GM_AT;

        #pragma unroll
        for (int ks = 0; ks < 4; ks++) {    // each ks = k32 fp8
            #pragma unroll
            for (int mi = 0; mi < 7; mi++)
                ldm4(a[mi], Ab + aoff + mi * (16 * GM_ROWB) + ks * 32);
            ldm4(b, Bb + boff + ks * 32);
            #pragma unroll
            for (int mi = 0; mi < 7; mi++)
                #pragma unroll
                for (int nj = 0; nj < 2; nj++)
                    mma_fp8(c[mi][nj], a[mi], b[nj * 2], b[nj * 2 + 1]);
        }
        if (++s == GM_NSTG) s = 0;
        if (++s2 == GM_NSTG) s2 = 0;
    }

    const int g = lane >> 2, tg = lane & 3;
    #pragma unroll
    for (int mi = 0; mi < 7; mi++) {
        const int row = bm + mi * 16 + g;
        #pragma unroll
        for (int nj = 0; nj < 2; nj++) {
            const int col = bn + wn + nj * 8 + tg * 2;
            *reinterpret_cast<float2*>(&g_spred[(size_t)row * DD + col]) =
                make_float2(c[mi][nj][0], c[mi][nj][1]);
            *reinterpret_cast<float2*>(&g_spred[(size_t)(row + 8) * DD + col]) =
                make_float2(c[mi][nj][2], c[mi][nj][3]);
        }
    }
}

// ---------------- kernel 3: L2-normalize -> fp16 (warp per row) --------------
__global__ void __launch_bounds__(512) k_normalize(const float* __restrict__ Emb,
                                                   const int* __restrict__ labels) {
    const int t = blockIdx.x * 16 + (threadIdx.x >> 5);   // 16 warps/blk, 1 row each
    const int lane = threadIdx.x & 31;
    // soft_pred row: 512 floats = 32 lanes x 4x float4
    float4 v[4];
    float ss = 0.0f;
    #pragma unroll
    for (int q = 0; q < 4; q++) {
        v[q] = reinterpret_cast<const float4*>(g_spred + (size_t)t * DD)[lane + q * 32];
        ss += v[q].x * v[q].x + v[q].y * v[q].y + v[q].z * v[q].z + v[q].w * v[q].w;
    }
    #pragma unroll
    for (int o = 16; o; o >>= 1) ss += __shfl_xor_sync(0xffffffffu, ss, o);
    float s = 1.0f / fmaxf(sqrtf(ss), 1e-12f);
    #pragma unroll
    for (int q = 0; q < 4; q++) {
        __half h[4] = { __float2half(v[q].x * s), __float2half(v[q].y * s),
                        __float2half(v[q].z * s), __float2half(v[q].w * s) };
        reinterpret_cast<uint2*>(g_pnh + (size_t)t * DD)[lane + q * 32] =
            *reinterpret_cast<uint2*>(h);
    }

    int lab = labels[t];
    if (lab == -100) lab = 0;
    float ss2 = 0.0f;
    float4 w[4];
    #pragma unroll
    for (int q = 0; q < 4; q++) {
        w[q] = reinterpret_cast<const float4*>(Emb + (size_t)lab * DD)[lane + q * 32];
        ss2 += w[q].x * w[q].x + w[q].y * w[q].y + w[q].z * w[q].z + w[q].w * w[q].w;
    }
    #pragma unroll
    for (int o = 16; o; o >>= 1) ss2 += __shfl_xor_sync(0xffffffffu, ss2, o);
    float s2 = 1.0f / fmaxf(sqrtf(ss2), 1e-12f);
    #pragma unroll
    for (int q = 0; q < 4; q++) {
        __half h2[4] = { __float2half(w[q].x * s2), __float2half(w[q].y * s2),
                         __float2half(w[q].z * s2), __float2half(w[q].w * s2) };
        reinterpret_cast<uint2*>(g_rnh + (size_t)t * DD)[lane + q * 32] =
            *reinterpret_cast<uint2*>(h2);
    }
}

// ---------------- kernel 4: sim = Pn @ Rn^T with fused masked row/col max ----
#define ROW_BYTES 144
#define TILE_BYTES (128 * ROW_BYTES)       /* 18432 */
#define STAGE_BYTES (2 * TILE_BYTES)       /* 36864 */
#define NSTAGE 4
#define SIM_SMEM (NSTAGE * STAGE_BYTES)    /* 147456 */
#define KC16 64
#define SIM_ITERS (DD / KC16)   /* 8 */

__global__ void __launch_bounds__(256) k_sim_mma(const int* __restrict__ labels) {
    extern __shared__ char smem[];
    __shared__ unsigned char validI[128], validJ[128];
    const uint32_t sbase = smem_u32(smem);
    const int tid = threadIdx.x;
    const int wid = tid >> 5, lane = tid & 31;
    const int b = blockIdx.z;
    const int bm = blockIdx.y * 128;   // pred rows i
    const int bn = blockIdx.x * 128;   // ref rows j
    const int wm = (wid & 1) * 64;
    const int wn = (wid >> 1) * 32;
    const __half* P = g_pnh + (size_t)b * TT * DD;
    const __half* R = g_rnh + (size_t)b * TT * DD;

    if (tid < 128) validI[tid] = (labels[b * TT + bm + tid] != -100) ? 1 : 0;
    else validJ[tid - 128] = (labels[b * TT + bn + tid - 128] != -100) ? 1 : 0;

    float c[4][4][4];
    #pragma unroll
    for (int i = 0; i < 4; i++)
        #pragma unroll
        for (int j = 0; j < 4; j++)
            #pragma unroll
            for (int q = 0; q < 4; q++) c[i][j][q] = 0.0f;

    const int msel = lane >> 3, rin = lane & 7;
    const uint32_t aoff = (uint32_t)((wm + ((msel & 1) << 3) + rin) * ROW_BYTES + ((msel >> 1) << 4));
    const uint32_t boff = (uint32_t)((wn + ((msel >> 1) << 3) + rin) * ROW_BYTES + ((msel & 1) << 4));

    auto stage_load = [&](int it) {
        const int s = it & (NSTAGE - 1);
        const int k0 = it * KC16;
        const uint32_t sb = sbase + s * STAGE_BYTES;
        #pragma unroll
        for (int i = 0; i < 4; i++) {
            int chunk = tid + (i << 8);
            int row = chunk >> 3, col = chunk & 7;
            uint32_t doff = (uint32_t)(row * ROW_BYTES + col * 16);
            cp16(sb + doff,              P + (size_t)(bm + row) * DD + k0 + col * 8);
            cp16(sb + TILE_BYTES + doff, R + (size_t)(bn + row) * DD + k0 + col * 8);
        }
        asm volatile("cp.async.commit_group;");
    };

    stage_load(0);
    stage_load(1);
    stage_load(2);

    for (int it = 0; it < SIM_ITERS; it++) {
        const int s = it & (NSTAGE - 1);
        asm volatile("cp.async.wait_group 2;");
        __syncthreads();

        if (it + 3 < SIM_ITERS) stage_load(it + 3);
        else asm volatile("cp.async.commit_group;");

        const uint32_t Ab = sbase + s * STAGE_BYTES;
        const uint32_t Bb = Ab + TILE_BYTES;

        #pragma unroll
        for (int ks = 0; ks < 4; ks++) {
            uint32_t a[4][4], bfr[2][4];
            #pragma unroll
            for (int mi = 0; mi < 4; mi++)
                ldm4(a[mi], Ab + aoff + mi * (16 * ROW_BYTES) + ks * 32);
            #pragma unroll
            for (int jj = 0; jj < 2; jj++)
                ldm4(bfr[jj], Bb + boff + jj * (16 * ROW_BYTES) + ks * 32);
            #pragma unroll
            for (int mi = 0; mi < 4; mi++)
                #pragma unroll
                for (int nj = 0; nj < 4; nj++) {
                    const uint32_t* bp = &bfr[nj >> 1][(nj & 1) * 2];
                    mma_f16(c[mi][nj], a[mi], bp[0], bp[1]);
                }
        }
    }

    const int g = lane >> 2, tg = lane & 3;

    // ---- fused masked row max (precision) ----
    #pragma unroll
    for (int mi = 0; mi < 4; mi++) {
        const int r0 = wm + mi * 16 + g;      // local row, and r0+8
        float rm0 = NEG_INF, rm1 = NEG_INF;
        #pragma unroll
        for (int nj = 0; nj < 4; nj++) {
            const int c0 = wn + nj * 8 + tg * 2;
            const bool j0 = validJ[c0], j1 = validJ[c0 + 1];
            rm0 = fmaxf(rm0, fmaxf(j0 ? c[mi][nj][0] : NEG_INF, j1 ? c[mi][nj][1] : NEG_INF));
            rm1 = fmaxf(rm1, fmaxf(j0 ? c[mi][nj][2] : NEG_INF, j1 ? c[mi][nj][3] : NEG_INF));
        }
        #pragma unroll
        for (int o = 1; o <= 2; o <<= 1) {
            rm0 = fmaxf(rm0, __shfl_xor_sync(0xffffffffu, rm0, o));
            rm1 = fmaxf(rm1, __shfl_xor_sync(0xffffffffu, rm1, o));
        }
        if (tg == 0) {
            atomicMax(&g_pmaxo[b * TT + bm + r0],     f2o(rm0));
            atomicMax(&g_pmaxo[b * TT + bm + r0 + 8], f2o(rm1));
        }
    }

    // ---- fused masked col max (recall) ----
    #pragma unroll
    for (int nj = 0; nj < 4; nj++) {
        const int c0 = wn + nj * 8 + tg * 2;
        float cm0 = NEG_INF, cm1 = NEG_INF;
        #pragma unroll
        for (int mi = 0; mi < 4; mi++) {
            const int r0 = wm + mi * 16 + g;
            const bool i0 = validI[r0], i1 = validI[r0 + 8];
            cm0 = fmaxf(cm0, fmaxf(i0 ? c[mi][nj][0] : NEG_INF, i1 ? c[mi][nj][2] : NEG_INF));
            cm1 = fmaxf(cm1, fmaxf(i0 ? c[mi][nj][1] : NEG_INF, i1 ? c[mi][nj][3] : NEG_INF));
        }
        #pragma unroll
        for (int o = 4; o <= 16; o <<= 1) {
            cm0 = fmaxf(cm0, __shfl_xor_sync(0xffffffffu, cm0, o));
            cm1 = fmaxf(cm1, __shfl_xor_sync(0xffffffffu, cm1, o));
        }
        if (g == 0) {
            atomicMax(&g_rmaxo[b * TT + bn + c0],     f2o(cm0));
            atomicMax(&g_rmaxo[b * TT + bn + c0 + 1], f2o(cm1));
        }
    }
}

// ---------------- kernel 6: final reduction ----------------
__global__ void k_final(const int* __restrict__ labels, float* __restrict__ out) {
    __shared__ float sp[256], sr[256], sc[256];
    const int tid = threadIdx.x;
    float total = 0.0f;
    for (int b = 0; b < BB; b++) {
        float psum = 0.0f, rsum = 0.0f, cnt = 0.0f;
        for (int idx = tid; idx < TT; idx += 256) {
            if (labels[b * TT + idx] != -100) {
                psum += o2f(g_pmaxo[b * TT + idx]);
                rsum += o2f(g_rmaxo[b * TT + idx]);
                cnt  += 1.0f;
            }
        }
        sp[tid] = psum; sr[tid] = rsum; sc[tid] = cnt;
        __syncthreads();
        for (int s = 128; s > 0; s >>= 1) {
            if (tid < s) {
                sp[tid] += sp[tid + s];
                sr[tid] += sr[tid + s];
                sc[tid] += sc[tid + s];
            }
            __syncthreads();
        }
        if (tid == 0) {
            float cntv = sc[0];
            float dc = fmaxf(cntv, 1.0f);
            float prec = sp[0] / dc;
            float rec  = sr[0] / dc;
            float den = prec + rec;
            float f1 = (den > 0.0f) ? (2.0f * prec * rec / fmaxf(den, 1e-8f)) : 0.0f;
            total += (cntv > 0.0f) ? (1.0f - f1) : 0.0f;
        }
        __syncthreads();
    }
    if (tid == 0) out[0] = total / (float)BB;
}

// ---------------- launch ----------------
extern "C" void kernel_launch(void* const* d_in, const int* in_sizes, int n_in,
                              void* d_out, int out_size) {
    const float* logits = (const float*)d_in[0];   // [8,512,32128] f32
    const int*   labels = (const int*)d_in[1];     // [8,512] i32
    const float* emb    = (const float*)d_in[2];   // [32128,512] f32
    float* out = (float*)d_out;

    cudaFuncSetAttribute(k_gemm8, cudaFuncAttributeMaxDynamicSharedMemorySize, GM_SMEM);
    cudaFuncSetAttribute(k_sim_mma, cudaFuncAttributeMaxDynamicSharedMemorySize, SIM_SMEM);

    k_prologue<<<PRO_GRID, 256>>>(logits, labels, emb);
    k_gemm8<<<148, 256, GM_SMEM>>>();
    k_normalize<<<MM / 16, 512>>>(emb, labels);
    k_sim_mma<<<dim3(TT / 128, TT / 128, BB), 256, SIM_SMEM>>>(labels);
    k_final<<<1, 256>>>(labels, out);
}

// round 15
// speedup vs baseline: 1.4721x; 1.0441x over previous
#include <cuda_runtime.h>
#include <cuda_fp16.h>
#include <cuda_fp8.h>
#include <math.h>
#include <stdint.h>

#define BB 8
#define TT 512
#define VV 32128
#define DD 512
#define MM (BB*TT)          /* 4096 tokens */
#define NEG_INF (-1e9f)

// ---------------- scratch (device globals; no allocations allowed) ----------
__device__ uint8_t  g_A8[(size_t)MM * VV];   // 131M e4m3 exp(l); zero-init => invalid rows stay 0
__device__ uint8_t  g_B8[(size_t)DD * VV];   // 16 MB e4m3 (E^T * 64)
__device__ float    g_spred[MM * DD];        // zeroed each launch (K-split atomic accum)
__device__ __half   g_pnh[MM * DD];
__device__ __half   g_rnh[MM * DD];
__device__ unsigned g_pmaxo[MM];             // ordered-uint encoded maxes
__device__ unsigned g_rmaxo[MM];

// ---------------- PTX helpers (legacy-ISA: family-target safe) ----------------
__device__ __forceinline__ uint32_t smem_u32(const void* p) {
    uint32_t a;
    asm("{ .reg .u64 t; cvta.to.shared.u64 t, %1; cvt.u32.u64 %0, t; }" : "=r"(a) : "l"(p));
    return a;
}
__device__ __forceinline__ void cp16(uint32_t dst, const void* src) {
    asm volatile("cp.async.cg.shared.global [%0], [%1], 16;" :: "r"(dst), "l"(src));
}
__device__ __forceinline__ void ldm4(uint32_t* r, uint32_t addr) {
    asm volatile("ldmatrix.sync.aligned.m8n8.x4.shared.b16 {%0,%1,%2,%3}, [%4];"
                 : "=r"(r[0]), "=r"(r[1]), "=r"(r[2]), "=r"(r[3]) : "r"(addr));
}
__device__ __forceinline__ void mma_fp8(float* c, const uint32_t* a, uint32_t b0, uint32_t b1) {
    asm volatile(
        "mma.sync.aligned.m16n8k32.row.col.f32.e4m3.e4m3.f32 "
        "{%0,%1,%2,%3}, {%4,%5,%6,%7}, {%8,%9}, {%0,%1,%2,%3};"
        : "+f"(c[0]), "+f"(c[1]), "+f"(c[2]), "+f"(c[3])
        : "r"(a[0]), "r"(a[1]), "r"(a[2]), "r"(a[3]), "r"(b0), "r"(b1));
}
__device__ __forceinline__ void mma_f16(float* c, const uint32_t* a, uint32_t b0, uint32_t b1) {
    asm volatile(
        "mma.sync.aligned.m16n8k16.row.col.f32.f16.f16.f32 "
        "{%0,%1,%2,%3}, {%4,%5,%6,%7}, {%8,%9}, {%0,%1,%2,%3};"
        : "+f"(c[0]), "+f"(c[1]), "+f"(c[2]), "+f"(c[3])
        : "r"(a[0]), "r"(a[1]), "r"(a[2]), "r"(a[3]), "r"(b0), "r"(b1));
}
// order-preserving float<->uint for atomicMax over signed floats
__device__ __forceinline__ unsigned f2o(float f) {
    unsigned b = __float_as_uint(f);
    return (b & 0x80000000u) ? ~b : (b | 0x80000000u);
}
__device__ __forceinline__ float o2f(unsigned u) {
    unsigned b = (u & 0x80000000u) ? (u ^ 0x80000000u) : ~u;
    return __uint_as_float(b);
}

// ---------------- fused prologue: init + zero spred + castB + exp8 ------------
#define PRO_INIT 16
#define PRO_ZERO 2048         /* MM*DD floats / (256 thr * 4) = 2048 CTAs */
#define PRO_CASTN 8032        /* (VV/32)*(DD/32)=16064 tiles / 2 per CTA */
#define CAST_VX (VV / 32)     /* 1004 */
#define PRO_GRID (PRO_INIT + PRO_ZERO + PRO_CASTN + MM)

__global__ void __launch_bounds__(256) k_prologue(const float* __restrict__ logits,
                                                  const int* __restrict__ labels,
                                                  const float* __restrict__ E) {
    const int bid = blockIdx.x;
    const int tid = threadIdx.x;

    if (bid < PRO_INIT) {
        int i = bid * 256 + tid;
        if (i < MM) { g_pmaxo[i] = 0u; g_rmaxo[i] = 0u; }
        return;
    }
    if (bid < PRO_INIT + PRO_ZERO) {
        int i = (bid - PRO_INIT) * 256 + tid;
        reinterpret_cast<float4*>(g_spred)[i] = make_float4(0.f, 0.f, 0.f, 0.f);
        return;
    }
    if (bid < PRO_INIT + PRO_ZERO + PRO_CASTN) {
        __shared__ float tile[2][32][33];
        const int t2 = (bid - PRO_INIT - PRO_ZERO) * 2;
        #pragma unroll
        for (int h = 0; h < 2; h++) {
            const int t = t2 + h;
            const int v0 = (t % CAST_VX) * 32, d0 = (t / CAST_VX) * 32;
            const int tx = tid & 31, ty = tid >> 5;
            for (int r = ty; r < 32; r += 8)
                tile[h][r][tx] = E[(size_t)(v0 + r) * DD + d0 + tx];
            __syncthreads();
            for (int r = ty; r < 32; r += 8) {
                __nv_fp8_e4m3 q(tile[h][tx][r] * 64.0f);
                g_B8[(size_t)(d0 + r) * VV + v0 + tx] = *reinterpret_cast<uint8_t*>(&q);
            }
            __syncthreads();
        }
        return;
    }
    // exp8 role
    const size_t row = bid - PRO_INIT - PRO_ZERO - PRO_CASTN;
    if (labels[row] == -100) return;      // A8 row stays zero (static init)
    const float* lr = logits + row * (size_t)VV;
    uint8_t* ar = g_A8 + row * (size_t)VV;
    for (int i = tid * 8; i < VV; i += 256 * 8) {
        float4 v1 = *reinterpret_cast<const float4*>(lr + i);
        float4 v2 = *reinterpret_cast<const float4*>(lr + i + 4);
        float4 e1 = make_float4(__expf(v1.x), __expf(v1.y), __expf(v1.z), __expf(v1.w));
        float4 e2 = make_float4(__expf(v2.x), __expf(v2.y), __expf(v2.z), __expf(v2.w));
        __nv_fp8x4_e4m3 p1(e1), p2(e2);
        uint2 o;
        o.x = *reinterpret_cast<uint32_t*>(&p1);
        o.y = *reinterpret_cast<uint32_t*>(&p2);
        *reinterpret_cast<uint2*>(ar + i) = o;
    }
}

// ---------------- kernel 2: K-split e4m3 GEMM, 2 CTAs/SM ----------------------
// C[4096,512] = exp(L) @ (E*64). Grid 296 = 37 M-tiles x 4 N-tiles x 2 K-halves.
// Identical 112x16 warp-tile inner loop as R11-best; each CTA covers half of K
// (126/125 iters) and atomically accumulates its partial tile into g_spred.
// Tests whether the GEMM is issue/latency-bound (2x warps -> faster) or
// tensor-pipe-bound (unchanged).
#define GM_KC 128
#define GM_ROWB 144                      /* 128 fp8 + 16B pad */
#define GM_AT (112 * GM_ROWB)            /* 16128 */
#define GM_BT (128 * GM_ROWB)            /* 18432 */
#define GM_STG (GM_AT + GM_BT)           /* 34560 */
#define GM_NSTG 3
#define GM_SMEM (GM_NSTG * GM_STG)       /* 103680; x2 CTAs = 207KB <= carveout */
#define GM_ITERS (VV / GM_KC)            /* 251 */
#define GM_KSPLIT 126                    /* kt=0: [0,126), kt=1: [126,251) */

__global__ void __launch_bounds__(256, 2) k_gemm8() {
    extern __shared__ char smem[];
    const uint32_t sbase = smem_u32(smem);
    const int tid = threadIdx.x;
    const int wid = tid >> 5, lane = tid & 31;
    const int mt = blockIdx.x >> 3;
    const int nt = (blockIdx.x >> 1) & 3;
    const int kt = blockIdx.x & 1;
    const int bm = (mt == 36) ? (MM - 112) : mt * 112;
    const int bn = nt * 128;
    const int wn = wid * 16;               // 8 warps cover 128 N
    const int it0 = kt ? GM_KSPLIT : 0;
    const int it1 = kt ? GM_ITERS : GM_KSPLIT;

    float c[7][2][4];
    #pragma unroll
    for (int i = 0; i < 7; i++)
        #pragma unroll
        for (int j = 0; j < 2; j++)
            #pragma unroll
            for (int q = 0; q < 4; q++) c[i][j][q] = 0.0f;

    const int msel = lane >> 3, rin = lane & 7;
    const uint32_t aoff = (uint32_t)((((msel & 1) << 3) + rin) * GM_ROWB + ((msel >> 1) << 4));
    const uint32_t boff = (uint32_t)((wn + ((msel >> 1) << 3) + rin) * GM_ROWB + ((msel & 1) << 4));

    auto stage_load = [&](int it, int s) {
        const int k0 = it * GM_KC;
        const uint32_t sb = sbase + s * GM_STG;
        #pragma unroll
        for (int i = 0; i < 8; i++) {
            int chunk = tid + (i << 8);
            if (chunk < 896) {
                int row = chunk >> 3, kc = chunk & 7;
                cp16(sb + row * GM_ROWB + kc * 16,
                     g_A8 + (size_t)(bm + row) * VV + k0 + kc * 16);
            } else if (chunk < 1920) {
                int ch = chunk - 896;
                int row = ch >> 3, kc = ch & 7;
                cp16(sb + GM_AT + row * GM_ROWB + kc * 16,
                     g_B8 + (size_t)(bn + row) * VV + k0 + kc * 16);
            }
        }
        asm volatile("cp.async.commit_group;");
    };

    stage_load(it0, 0);
    stage_load(it0 + 1, 1);

    uint32_t a[7][4], b[4];
    int s = 0, s2 = 2;

    for (int it = it0; it < it1; it++) {
        asm volatile("cp.async.wait_group 1;");
        __syncthreads();

        if (it + 2 < it1) stage_load(it + 2, s2);
        else asm volatile("cp.async.commit_group;");

        const uint32_t Ab = sbase + s * GM_STG;
        const uint32_t Bb = Ab + GM_AT;

        #pragma unroll
        for (int ks = 0; ks < 4; ks++) {    // each ks = k32 fp8
            #pragma unroll
            for (int mi = 0; mi < 7; mi++)
                ldm4(a[mi], Ab + aoff + mi * (16 * GM_ROWB) + ks * 32);
            ldm4(b, Bb + boff + ks * 32);
            #pragma unroll
            for (int mi = 0; mi < 7; mi++)
                #pragma unroll
                for (int nj = 0; nj < 2; nj++)
                    mma_fp8(c[mi][nj], a[mi], b[nj * 2], b[nj * 2 + 1]);
        }
        if (++s == GM_NSTG) s = 0;
        if (++s2 == GM_NSTG) s2 = 0;
    }

    // K-split epilogue: atomic accumulate partial tile.
    // NOTE: the overlapped last M-tile (mt==36 vs mt==35 rows 3984..4031) would
    // double-count with atomics, so mt==36 skips rows below MM-112+? -- rows
    // 3984..4095 belong to mt36 (bm=3984); mt35 covers 3920..4031: overlap
    // rows 3984..4031 are written by BOTH -> must be guarded. mt35 owns rows
    // < 3984; mt36 owns rows >= 3984.
    const int g = lane >> 2, tg = lane & 3;
    const int row_lo = (mt == 36) ? (MM - 112) : 0;          // always bm
    const int own_lo = (mt == 35) ? 0    : row_lo;           // unused helper
    (void)own_lo;
    #pragma unroll
    for (int mi = 0; mi < 7; mi++) {
        const int row  = bm + mi * 16 + g;
        const int row2 = row + 8;
        // ownership guard for the overlapped region (rows 3920..4031):
        const bool own1 = (mt == 36) ? (row  >= 3984) : !(mt == 35 && row  >= 3984);
        const bool own2 = (mt == 36) ? (row2 >= 3984) : !(mt == 35 && row2 >= 3984);
        #pragma unroll
        for (int nj = 0; nj < 2; nj++) {
            const int col = bn + wn + nj * 8 + tg * 2;
            if (own1) {
                atomicAdd(&g_spred[(size_t)row * DD + col],     c[mi][nj][0]);
                atomicAdd(&g_spred[(size_t)row * DD + col + 1], c[mi][nj][1]);
            }
            if (own2) {
                atomicAdd(&g_spred[(size_t)row2 * DD + col],     c[mi][nj][2]);
                atomicAdd(&g_spred[(size_t)row2 * DD + col + 1], c[mi][nj][3]);
            }
        }
    }
}

// ---------------- kernel 3: L2-normalize -> fp16 (warp per row) --------------
__global__ void __launch_bounds__(512) k_normalize(const float* __restrict__ Emb,
                                                   const int* __restrict__ labels) {
    const int t = blockIdx.x * 16 + (threadIdx.x >> 5);   // 16 warps/blk, 1 row each
    const int lane = threadIdx.x & 31;
    float4 v[4];
    float ss = 0.0f;
    #pragma unroll
    for (int q = 0; q < 4; q++) {
        v[q] = reinterpret_cast<const float4*>(g_spred + (size_t)t * DD)[lane + q * 32];
        ss += v[q].x * v[q].x + v[q].y * v[q].y + v[q].z * v[q].z + v[q].w * v[q].w;
    }
    #pragma unroll
    for (int o = 16; o; o >>= 1) ss += __shfl_xor_sync(0xffffffffu, ss, o);
    float s = 1.0f / fmaxf(sqrtf(ss), 1e-12f);
    #pragma unroll
    for (int q = 0; q < 4; q++) {
        __half h[4] = { __float2half(v[q].x * s), __float2half(v[q].y * s),
                        __float2half(v[q].z * s), __float2half(v[q].w * s) };
        reinterpret_cast<uint2*>(g_pnh + (size_t)t * DD)[lane + q * 32] =
            *reinterpret_cast<uint2*>(h);
    }

    int lab = labels[t];
    if (lab == -100) lab = 0;
    float ss2 = 0.0f;
    float4 w[4];
    #pragma unroll
    for (int q = 0; q < 4; q++) {
        w[q] = reinterpret_cast<const float4*>(Emb + (size_t)lab * DD)[lane + q * 32];
        ss2 += w[q].x * w[q].x + w[q].y * w[q].y + w[q].z * w[q].z + w[q].w * w[q].w;
    }
    #pragma unroll
    for (int o = 16; o; o >>= 1) ss2 += __shfl_xor_sync(0xffffffffu, ss2, o);
    float s2 = 1.0f / fmaxf(sqrtf(ss2), 1e-12f);
    #pragma unroll
    for (int q = 0; q < 4; q++) {
        __half h2[4] = { __float2half(w[q].x * s2), __float2half(w[q].y * s2),
                         __float2half(w[q].z * s2), __float2half(w[q].w * s2) };
        reinterpret_cast<uint2*>(g_rnh + (size_t)t * DD)[lane + q * 32] =
            *reinterpret_cast<uint2*>(h2);
    }
}

// ---------------- kernel 4: sim = Pn @ Rn^T with fused masked row/col max ----
#define ROW_BYTES 144
#define TILE_BYTES (128 * ROW_BYTES)       /* 18432 */
#define STAGE_BYTES (2 * TILE_BYTES)       /* 36864 */
#define NSTAGE 4
#define SIM_SMEM (NSTAGE * STAGE_BYTES)    /* 147456 */
#define KC16 64
#define SIM_ITERS (DD / KC16)   /* 8 */

__global__ void __launch_bounds__(256) k_sim_mma(const int* __restrict__ labels) {
    extern __shared__ char smem[];
    __shared__ unsigned char validI[128], validJ[128];
    const uint32_t sbase = smem_u32(smem);
    const int tid = threadIdx.x;
    const int wid = tid >> 5, lane = tid & 31;
    const int b = blockIdx.z;
    const int bm = blockIdx.y * 128;   // pred rows i
    const int bn = blockIdx.x * 128;   // ref rows j
    const int wm = (wid & 1) * 64;
    const int wn = (wid >> 1) * 32;
    const __half* P = g_pnh + (size_t)b * TT * DD;
    const __half* R = g_rnh + (size_t)b * TT * DD;

    if (tid < 128) validI[tid] = (labels[b * TT + bm + tid] != -100) ? 1 : 0;
    else validJ[tid - 128] = (labels[b * TT + bn + tid - 128] != -100) ? 1 : 0;

    float c[4][4][4];
    #pragma unroll
    for (int i = 0; i < 4; i++)
        #pragma unroll
        for (int j = 0; j < 4; j++)
            #pragma unroll
            for (int q = 0; q < 4; q++) c[i][j][q] = 0.0f;

    const int msel = lane >> 3, rin = lane & 7;
    const uint32_t aoff = (uint32_t)((wm + ((msel & 1) << 3) + rin) * ROW_BYTES + ((msel >> 1) << 4));
    const uint32_t boff = (uint32_t)((wn + ((msel >> 1) << 3) + rin) * ROW_BYTES + ((msel & 1) << 4));

    auto stage_load = [&](int it) {
        const int s = it & (NSTAGE - 1);
        const int k0 = it * KC16;
        const uint32_t sb = sbase + s * STAGE_BYTES;
        #pragma unroll
        for (int i = 0; i < 4; i++) {
            int chunk = tid + (i << 8);
            int row = chunk >> 3, col = chunk & 7;
            uint32_t doff = (uint32_t)(row * ROW_BYTES + col * 16);
            cp16(sb + doff,              P + (size_t)(bm + row) * DD + k0 + col * 8);
            cp16(sb + TILE_BYTES + doff, R + (size_t)(bn + row) * DD + k0 + col * 8);
        }
        asm volatile("cp.async.commit_group;");
    };

    stage_load(0);
    stage_load(1);
    stage_load(2);

    for (int it = 0; it < SIM_ITERS; it++) {
        const int s = it & (NSTAGE - 1);
        asm volatile("cp.async.wait_group 2;");
        __syncthreads();

        if (it + 3 < SIM_ITERS) stage_load(it + 3);
        else asm volatile("cp.async.commit_group;");

        const uint32_t Ab = sbase + s * STAGE_BYTES;
        const uint32_t Bb = Ab + TILE_BYTES;

        #pragma unroll
        for (int ks = 0; ks < 4; ks++) {
            uint32_t a[4][4], bfr[2][4];
            #pragma unroll
            for (int mi = 0; mi < 4; mi++)
                ldm4(a[mi], Ab + aoff + mi * (16 * ROW_BYTES) + ks * 32);
            #pragma unroll
            for (int jj = 0; jj < 2; jj++)
                ldm4(bfr[jj], Bb + boff + jj * (16 * ROW_BYTES) + ks * 32);
            #pragma unroll
            for (int mi = 0; mi < 4; mi++)
                #pragma unroll
                for (int nj = 0; nj < 4; nj++) {
                    const uint32_t* bp = &bfr[nj >> 1][(nj & 1) * 2];
                    mma_f16(c[mi][nj], a[mi], bp[0], bp[1]);
                }
        }
    }

    const int g = lane >> 2, tg = lane & 3;

    // ---- fused masked row max (precision) ----
    #pragma unroll
    for (int mi = 0; mi < 4; mi++) {
        const int r0 = wm + mi * 16 + g;      // local row, and r0+8
        float rm0 = NEG_INF, rm1 = NEG_INF;
        #pragma unroll
        for (int nj = 0; nj < 4; nj++) {
            const int c0 = wn + nj * 8 + tg * 2;
            const bool j0 = validJ[c0], j1 = validJ[c0 + 1];
            rm0 = fmaxf(rm0, fmaxf(j0 ? c[mi][nj][0] : NEG_INF, j1 ? c[mi][nj][1] : NEG_INF));
            rm1 = fmaxf(rm1, fmaxf(j0 ? c[mi][nj][2] : NEG_INF, j1 ? c[mi][nj][3] : NEG_INF));
        }
        #pragma unroll
        for (int o = 1; o <= 2; o <<= 1) {
            rm0 = fmaxf(rm0, __shfl_xor_sync(0xffffffffu, rm0, o));
            rm1 = fmaxf(rm1, __shfl_xor_sync(0xffffffffu, rm1, o));
        }
        if (tg == 0) {
            atomicMax(&g_pmaxo[b * TT + bm + r0],     f2o(rm0));
            atomicMax(&g_pmaxo[b * TT + bm + r0 + 8], f2o(rm1));
        }
    }

    // ---- fused masked col max (recall) ----
    #pragma unroll
    for (int nj = 0; nj < 4; nj++) {
        const int c0 = wn + nj * 8 + tg * 2;
        float cm0 = NEG_INF, cm1 = NEG_INF;
        #pragma unroll
        for (int mi = 0; mi < 4; mi++) {
            const int r0 = wm + mi * 16 + g;
            const bool i0 = validI[r0], i1 = validI[r0 + 8];
            cm0 = fmaxf(cm0, fmaxf(i0 ? c[mi][nj][0] : NEG_INF, i1 ? c[mi][nj][2] : NEG_INF));
            cm1 = fmaxf(cm1, fmaxf(i0 ? c[mi][nj][1] : NEG_INF, i1 ? c[mi][nj][3] : NEG_INF));
        }
        #pragma unroll
        for (int o = 4; o <= 16; o <<= 1) {
            cm0 = fmaxf(cm0, __shfl_xor_sync(0xffffffffu, cm0, o));
            cm1 = fmaxf(cm1, __shfl_xor_sync(0xffffffffu, cm1, o));
        }
        if (g == 0) {
            atomicMax(&g_rmaxo[b * TT + bn + c0],     f2o(cm0));
            atomicMax(&g_rmaxo[b * TT + bn + c0 + 1], f2o(cm1));
        }
    }
}

// ---------------- kernel 6: final reduction ----------------
__global__ void k_final(const int* __restrict__ labels, float* __restrict__ out) {
    __shared__ float sp[256], sr[256], sc[256];
    const int tid = threadIdx.x;
    float total = 0.0f;
    for (int b = 0; b < BB; b++) {
        float psum = 0.0f, rsum = 0.0f, cnt = 0.0f;
        for (int idx = tid; idx < TT; idx += 256) {
            if (labels[b * TT + idx] != -100) {
                psum += o2f(g_pmaxo[b * TT + idx]);
                rsum += o2f(g_rmaxo[b * TT + idx]);
                cnt  += 1.0f;
            }
        }
        sp[tid] = psum; sr[tid] = rsum; sc[tid] = cnt;
        __syncthreads();
        for (int s = 128; s > 0; s >>= 1) {
            if (tid < s) {
                sp[tid] += sp[tid + s];
                sr[tid] += sr[tid + s];
                sc[tid] += sc[tid + s];
            }
            __syncthreads();
        }
        if (tid == 0) {
            float cntv = sc[0];
            float dc = fmaxf(cntv, 1.0f);
            float prec = sp[0] / dc;
            float rec  = sr[0] / dc;
            float den = prec + rec;
            float f1 = (den > 0.0f) ? (2.0f * prec * rec / fmaxf(den, 1e-8f)) : 0.0f;
            total += (cntv > 0.0f) ? (1.0f - f1) : 0.0f;
        }
        __syncthreads();
    }
    if (tid == 0) out[0] = total / (float)BB;
}

// ---------------- launch ----------------
extern "C" void kernel_launch(void* const* d_in, const int* in_sizes, int n_in,
                              void* d_out, int out_size) {
    const float* logits = (const float*)d_in[0];   // [8,512,32128] f32
    const int*   labels = (const int*)d_in[1];     // [8,512] i32
    const float* emb    = (const float*)d_in[2];   // [32128,512] f32
    float* out = (float*)d_out;

    cudaFuncSetAttribute(k_gemm8, cudaFuncAttributeMaxDynamicSharedMemorySize, GM_SMEM);
    cudaFuncSetAttribute(k_sim_mma, cudaFuncAttributeMaxDynamicSharedMemorySize, SIM_SMEM);

    k_prologue<<<PRO_GRID, 256>>>(logits, labels, emb);
    k_gemm8<<<296, 256, GM_SMEM>>>();
    k_normalize<<<MM / 16, 512>>>(emb, labels);
    k_sim_mma<<<dim3(TT / 128, TT / 128, BB), 256, SIM_SMEM>>>(labels);
    k_final<<<1, 256>>>(labels, out);
}